// round 2
// baseline (speedup 1.0000x reference)
#include <cuda_runtime.h>

#define IMG_H 1024
#define IMG_W 1024
#define NBATCH 16
#define NPIX (NBATCH * IMG_H * IMG_W)
#define OVF_CAP (1u << 22)

// ---------------- scratch (static device globals; no allocation) ----------------
__device__ float    g_tu[NPIX];          // unnormalized "thin" (NMS-surviving magnitude)
__device__ unsigned g_bmax[NBATCH];      // per-batch max |grad| (float bits)
__device__ unsigned g_tumax[NBATCH];     // per-batch max thin_u (float bits)
__device__ unsigned g_ovfn[2];           // overflow queue counts (ping-pong)
__device__ unsigned g_ovfq[2][OVF_CAP];  // overflow queues
__device__ unsigned g_bar_cnt;           // grid barrier
__device__ unsigned g_bar_gen;

__constant__ int c_dy[8] = {0, 1, 1, 1, 0, -1, -1, -1};
__constant__ int c_dx[8] = {1, 1, 0, -1, -1, -1, 0, 1};

#define GW0 0.13533528323661270f   // exp(-2)
#define GW1 0.60653065971263342f   // exp(-0.5)
#define T1C 0.41421356237309503f   // tan(22.5 deg)
#define T2C 2.41421356237309510f   // tan(67.5 deg)
#define LOW_T_C 0.00392f
#define HIGH_T_C 0.15f
#define STRONG_BITS 0x437F0000u    // 255.0f

// ---------------- K0: reset scalars ----------------
__global__ void k_init() {
    int t = threadIdx.x;
    if (t < NBATCH) { g_bmax[t] = 0u; g_tumax[t] = 0u; }
    if (t < 2) g_ovfn[t] = 0u;
    if (t == 0) { g_bar_cnt = 0u; g_bar_gen = 0u; }
}

// ---------------- K1: fused blur + sobel + mag + NMS (+ zero d_out, batch maxima) ----
__global__ __launch_bounds__(1024) void k_front(const float* __restrict__ img,
                                                float* __restrict__ out) {
    __shared__ float sA[40 * 40];   // img tile, later S (blurred, stride 36)
    __shared__ float sB[40 * 36];   // H (h-blur), later mag (stride 34)
    __shared__ float red1[32], red2[32];

    const int bb  = blockIdx.z;
    const int gy0 = blockIdx.y << 5, gx0 = blockIdx.x << 5;
    const int tx = threadIdx.x, ty = threadIdx.y;
    const int tid = (ty << 5) | tx;
    const float* im = img + bb * (IMG_H * IMG_W);

    // load 40x40 img tile, zero-padded (origin gy0-4, gx0-4)
    for (int i = tid; i < 1600; i += 1024) {
        int ay = i / 40, ax = i - ay * 40;
        int gy = gy0 - 4 + ay, gx = gx0 - 4 + ax;
        float v = 0.f;
        if ((unsigned)gy < IMG_H && (unsigned)gx < IMG_W) v = __ldg(&im[gy * IMG_W + gx]);
        sA[i] = v;
    }
    __syncthreads();

    // horizontal blur: 40 rows x 36 cols -> sB
    for (int i = tid; i < 1440; i += 1024) {
        int hy = i / 36, hx = i - hy * 36;
        const float* r = &sA[hy * 40 + hx];
        sB[i] = GW0 * r[0] + GW1 * r[1] + r[2] + GW1 * r[3] + GW0 * r[4];
    }
    __syncthreads();

    // vertical blur: 36x36 S -> sA (stride 36). Zero outside image (sobel zero-pad).
    for (int i = tid; i < 1296; i += 1024) {
        int sy = i / 36, sx = i - sy * 36;
        const float* r = &sB[sy * 36 + sx];
        float v = GW0 * r[0] + GW1 * r[36] + r[72] + GW1 * r[108] + GW0 * r[144];
        int gy = gy0 - 2 + sy, gx = gx0 - 2 + sx;
        if ((unsigned)gy >= IMG_H || (unsigned)gx >= IMG_W) v = 0.f;
        sA[sy * 36 + sx] = v;
    }
    __syncthreads();

    // magnitude on 34x34 halo region -> sB (stride 34). Zero outside image (NMS zero-pad).
    for (int i = tid; i < 1156; i += 1024) {
        int my = i / 34, mx = i - my * 34;
        float m = 0.f;
        int gy = gy0 - 1 + my, gx = gx0 - 1 + mx;
        if ((unsigned)gy < IMG_H && (unsigned)gx < IMG_W) {
            const float* s = &sA[my * 36 + mx];
            float s00 = s[0],  s01 = s[1],  s02 = s[2];
            float s10 = s[36],              s12 = s[38];
            float s20 = s[72], s21 = s[73], s22 = s[74];
            float gxv = (s00 - s02) + 2.f * (s10 - s12) + (s20 - s22);
            float gyv = (s00 + 2.f * s01 + s02) - (s20 + 2.f * s21 + s22);
            m = sqrtf(gxv * gxv + gyv * gyv);
        }
        sB[my * 34 + mx] = m;
    }
    __syncthreads();

    // per-output-pixel: recompute Ix/Iy for direction, NMS via octant comparisons
    const float* s = &sA[(ty + 1) * 36 + (tx + 1)];
    float s00 = s[0],  s01 = s[1],  s02 = s[2];
    float s10 = s[36],              s12 = s[38];
    float s20 = s[72], s21 = s[73], s22 = s[74];
    float Ix = (s00 - s02) + 2.f * (s10 - s12) + (s20 - s22);
    float Iy = (s00 + 2.f * s01 + s02) - (s20 + 2.f * s21 + s22);
    float mc = sB[(ty + 1) * 34 + (tx + 1)];

    // sector index k == rint((atan2(Iy,Ix)*180/3.1415926 + 180)/45) % 8
    float axv = fabsf(Ix), ayv = fabsf(Iy);
    int k;
    if (ayv <= T1C * axv)       k = (Ix >= 0.f) ? 4 : 0;
    else if (ayv >= T2C * axv)  k = (Iy > 0.f) ? 6 : 2;
    else                        k = (Iy > 0.f) ? ((Ix > 0.f) ? 5 : 7)
                                               : ((Ix > 0.f) ? 3 : 1);
    int dy = c_dy[k], dx = c_dx[k];
    float mp = sB[(ty + 1 + dy) * 34 + (tx + 1 + dx)];
    float mn = sB[(ty + 1 - dy) * 34 + (tx + 1 - dx)];
    float tu = (fminf(mc - mp, mc - mn) > 0.f) ? mc : 0.f;

    unsigned p = ((unsigned)bb << 20) | ((unsigned)(gy0 + ty) << 10) | (unsigned)(gx0 + tx);
    g_tu[p] = tu;
    out[p]  = 0.f;

    // block-reduce per-batch maxima
    float bm = mc, tm = tu;
    for (int o = 16; o; o >>= 1) {
        bm = fmaxf(bm, __shfl_xor_sync(0xffffffffu, bm, o));
        tm = fmaxf(tm, __shfl_xor_sync(0xffffffffu, tm, o));
    }
    if ((tid & 31) == 0) { red1[tid >> 5] = bm; red2[tid >> 5] = tm; }
    __syncthreads();
    if (tid < 32) {
        bm = red1[tid]; tm = red2[tid];
        for (int o = 16; o; o >>= 1) {
            bm = fmaxf(bm, __shfl_xor_sync(0xffffffffu, bm, o));
            tm = fmaxf(tm, __shfl_xor_sync(0xffffffffu, tm, o));
        }
        if (tid == 0) {
            atomicMax(&g_bmax[bb],  __float_as_uint(bm));
            atomicMax(&g_tumax[bb], __float_as_uint(tm));
        }
    }
}

// ---------------- flood-fill expansion (claim via CAS, DFS with local stack) -------
__device__ __forceinline__ void expand_from(unsigned seed, float* out, float hi,
                                            float bm, int qidx, int maxpops) {
    unsigned stk[96];
    int sp = 0, pops = 0;
    unsigned cur = seed;
    const unsigned base = cur & ~0xFFFFFu;
    while (true) {
        int y = (cur >> 10) & 1023;
        int x = cur & 1023;
#pragma unroll
        for (int d = 0; d < 8; d++) {
            int ny = y + c_dy[d], nx = x + c_dx[d];
            if ((unsigned)ny < IMG_H && (unsigned)nx < IMG_W) {
                unsigned n = base | ((unsigned)ny << 10) | (unsigned)nx;
                float t = __ldg(&g_tu[n]) / bm;
                if (t < hi && t >= LOW_T_C) {
                    unsigned old = atomicCAS((unsigned*)&out[n], 0u, STRONG_BITS);
                    if (old == 0u) {
                        if (sp < 96) stk[sp++] = n;
                        else {
                            unsigned pos = atomicAdd(&g_ovfn[qidx], 1u);
                            if (pos < OVF_CAP) g_ovfq[qidx][pos] = n;
                        }
                    }
                }
            }
        }
        if (sp == 0) break;
        if (++pops > maxpops) {  // defer remainder to the drain kernel
            while (sp > 0) {
                unsigned v = stk[--sp];
                unsigned pos = atomicAdd(&g_ovfn[qidx], 1u);
                if (pos < OVF_CAP) g_ovfq[qidx][pos] = v;
            }
            break;
        }
        cur = stk[--sp];
    }
}

__device__ __forceinline__ float compute_hi() {
    float tmax = 0.f;
#pragma unroll
    for (int bb = 0; bb < NBATCH; bb++) {
        float bmv = __uint_as_float(g_bmax[bb]);
        float tmv = __uint_as_float(g_tumax[bb]);
        if (bmv > 0.f) tmax = fmaxf(tmax, tmv / bmv);
    }
    return tmax * HIGH_T_C;
}

// ---------------- K2: seed strong pixels + flood fill ------------------------------
__global__ __launch_bounds__(256) void k_seed(float* __restrict__ out) {
    const float hi = compute_hi();
    const unsigned stride = gridDim.x * blockDim.x;
    for (unsigned p = blockIdx.x * blockDim.x + threadIdx.x; p < NPIX; p += stride) {
        int bb = p >> 20;
        float bmv = __uint_as_float(g_bmax[bb]);
        float v = __ldg(&g_tu[p]) / bmv;
        if (v >= hi) {
            out[p] = 255.0f;
            expand_from(p, out, hi, bmv, 0, 4096);
        }
    }
}

// ---------------- K3: persistent drain of overflow queue (grid barrier) ------------
__device__ __forceinline__ void gsync() {
    __syncthreads();
    if (threadIdx.x == 0) {
        unsigned gen = atomicAdd(&g_bar_gen, 0u);
        __threadfence();
        if (atomicAdd(&g_bar_cnt, 1u) == gridDim.x - 1) {
            atomicExch(&g_bar_cnt, 0u);
            __threadfence();
            atomicAdd(&g_bar_gen, 1u);
        } else {
            while (atomicAdd(&g_bar_gen, 0u) == gen) __nanosleep(200);
        }
        __threadfence();
    }
    __syncthreads();
}

__global__ __launch_bounds__(256) void k_drain(float* __restrict__ out) {
    const float hi = compute_hi();
    int curq = 0;
    while (true) {
        unsigned n = atomicAdd(&g_ovfn[curq], 0u);
        if (n == 0u) break;
        if (n > OVF_CAP) n = OVF_CAP;
        const unsigned stride = gridDim.x * blockDim.x;
        for (unsigned i = blockIdx.x * blockDim.x + threadIdx.x; i < n; i += stride) {
            unsigned p = __ldcg(&g_ovfq[curq][i]);
            int bb = p >> 20;
            float bmv = __uint_as_float(g_bmax[bb]);
            expand_from(p, out, hi, bmv, curq ^ 1, 100000);
        }
        gsync();
        if (blockIdx.x == 0 && threadIdx.x == 0) atomicExch(&g_ovfn[curq], 0u);
        gsync();
        curq ^= 1;
    }
}

// ---------------- launch ----------------
extern "C" void kernel_launch(void* const* d_in, const int* in_sizes, int n_in,
                              void* d_out, int out_size) {
    const float* img = (const float*)d_in[0];
    float* out = (float*)d_out;
    (void)in_sizes; (void)n_in; (void)out_size;

    k_init<<<1, 32>>>();
    dim3 b1(32, 32), g1(IMG_W / 32, IMG_H / 32, NBATCH);
    k_front<<<g1, b1>>>(img, out);
    k_seed<<<4096, 256>>>(out);
    k_drain<<<120, 256>>>(out);   // 120 blocks <= 148 SMs: residency guaranteed for grid barrier
}

// round 4
// speedup vs baseline: 1.2868x; 1.2868x over previous
#include <cuda_runtime.h>

#define IMG_H 1024
#define IMG_W 1024
#define NBATCH 16
#define NPIX (NBATCH * IMG_H * IMG_W)
#define OVF_CAP (1u << 23)

// ---------------- scratch (static device globals; no allocation) ----------------
__device__ float    g_tu[NPIX];          // SQUARED NMS-surviving magnitude (thin^2, unnormalized)
__device__ unsigned g_bmax[NBATCH];      // per-batch max mag^2 (float bits)
__device__ unsigned g_tumax[NBATCH];     // per-batch max thin^2 (float bits)
__device__ float    g_lo2[NBATCH];       // (LOW_T * bmax)^2
__device__ float    g_hi2[NBATCH];       // (hi * bmax)^2
__device__ unsigned g_ovfn[2];           // spill queue counts (ping-pong)
__device__ unsigned g_ovfq[2][OVF_CAP];  // spill queues
__device__ unsigned g_bar_cnt;           // grid barrier
__device__ unsigned g_bar_gen;

__constant__ int c_dy[8] = {0, 1, 1, 1, 0, -1, -1, -1};
__constant__ int c_dx[8] = {1, 1, 0, -1, -1, -1, 0, 1};

#define GW0 0.13533528323661270f   // exp(-2)
#define GW1 0.60653065971263342f   // exp(-0.5)
#define T1C 0.41421356237309503f   // tan(22.5 deg)
#define T2C 2.41421356237309510f   // tan(67.5 deg)
#define LOW_T_C 0.00392f
#define HIGH_T_C 0.15f
#define STRONG_BITS 0x437F0000u    // 255.0f

// ---------------- K0: reset scalars ----------------
__global__ void k_init() {
    int t = threadIdx.x;
    if (t < NBATCH) { g_bmax[t] = 0u; g_tumax[t] = 0u; }
    if (t < 2) g_ovfn[t] = 0u;
    if (t == 0) { g_bar_cnt = 0u; g_bar_gen = 0u; }
}

// ---------------- K1: fused blur + sobel + mag^2 + NMS (+ zero d_out, batch maxima) ----
__global__ __launch_bounds__(1024) void k_front(const float* __restrict__ img,
                                                float* __restrict__ out) {
    __shared__ float sA[40 * 40];   // img tile, later S (blurred, stride 36)
    __shared__ float sB[40 * 36];   // H (h-blur), later mag^2 (stride 34)
    __shared__ float red1[32], red2[32];

    const int bb  = blockIdx.z;
    const int gy0 = blockIdx.y << 5, gx0 = blockIdx.x << 5;
    const int tx = threadIdx.x, ty = threadIdx.y;
    const int tid = (ty << 5) | tx;
    const float* im = img + bb * (IMG_H * IMG_W);

    // load 40x40 img tile, zero-padded (origin gy0-4, gx0-4)
    for (int i = tid; i < 1600; i += 1024) {
        int ay = i / 40, ax = i - ay * 40;
        int gy = gy0 - 4 + ay, gx = gx0 - 4 + ax;
        float v = 0.f;
        if ((unsigned)gy < IMG_H && (unsigned)gx < IMG_W) v = __ldg(&im[gy * IMG_W + gx]);
        sA[i] = v;
    }
    __syncthreads();

    // horizontal blur: 40 rows x 36 cols -> sB
    for (int i = tid; i < 1440; i += 1024) {
        int hy = i / 36, hx = i - hy * 36;
        const float* r = &sA[hy * 40 + hx];
        sB[i] = GW0 * r[0] + GW1 * r[1] + r[2] + GW1 * r[3] + GW0 * r[4];
    }
    __syncthreads();

    // vertical blur: 36x36 S -> sA (stride 36). Zero outside image (sobel zero-pad).
    for (int i = tid; i < 1296; i += 1024) {
        int sy = i / 36, sx = i - sy * 36;
        const float* r = &sB[sy * 36 + sx];
        float v = GW0 * r[0] + GW1 * r[36] + r[72] + GW1 * r[108] + GW0 * r[144];
        int gy = gy0 - 2 + sy, gx = gx0 - 2 + sx;
        if ((unsigned)gy >= IMG_H || (unsigned)gx >= IMG_W) v = 0.f;
        sA[sy * 36 + sx] = v;
    }
    __syncthreads();

    // mag^2 on 34x34 halo region -> sB (stride 34). Zero outside image (NMS zero-pad).
    for (int i = tid; i < 1156; i += 1024) {
        int my = i / 34, mx = i - my * 34;
        float m = 0.f;
        int gy = gy0 - 1 + my, gx = gx0 - 1 + mx;
        if ((unsigned)gy < IMG_H && (unsigned)gx < IMG_W) {
            const float* s = &sA[my * 36 + mx];
            float s00 = s[0],  s01 = s[1],  s02 = s[2];
            float s10 = s[36],              s12 = s[38];
            float s20 = s[72], s21 = s[73], s22 = s[74];
            float gxv = (s00 - s02) + 2.f * (s10 - s12) + (s20 - s22);
            float gyv = (s00 + 2.f * s01 + s02) - (s20 + 2.f * s21 + s22);
            m = gxv * gxv + gyv * gyv;           // squared magnitude — no sqrt
        }
        sB[my * 34 + mx] = m;
    }
    __syncthreads();

    // per-output-pixel: recompute Ix/Iy for direction, NMS via octant comparisons on m^2
    const float* s = &sA[(ty + 1) * 36 + (tx + 1)];
    float s00 = s[0],  s01 = s[1],  s02 = s[2];
    float s10 = s[36],              s12 = s[38];
    float s20 = s[72], s21 = s[73], s22 = s[74];
    float Ix = (s00 - s02) + 2.f * (s10 - s12) + (s20 - s22);
    float Iy = (s00 + 2.f * s01 + s02) - (s20 + 2.f * s21 + s22);
    float mc = sB[(ty + 1) * 34 + (tx + 1)];

    // sector index k == rint((atan2(Iy,Ix)*180/pi + 180)/45) % 8
    float axv = fabsf(Ix), ayv = fabsf(Iy);
    int k;
    if (ayv <= T1C * axv)       k = (Ix >= 0.f) ? 4 : 0;
    else if (ayv >= T2C * axv)  k = (Iy > 0.f) ? 6 : 2;
    else                        k = (Iy > 0.f) ? ((Ix > 0.f) ? 5 : 7)
                                               : ((Ix > 0.f) ? 3 : 1);
    int dy = c_dy[k], dx = c_dx[k];
    float mp = sB[(ty + 1 + dy) * 34 + (tx + 1 + dx)];
    float mn = sB[(ty + 1 - dy) * 34 + (tx + 1 - dx)];
    float tu = (mc > mp && mc > mn) ? mc : 0.f;   // NMS on squares (sqrt monotone)

    unsigned p = ((unsigned)bb << 20) | ((unsigned)(gy0 + ty) << 10) | (unsigned)(gx0 + tx);
    g_tu[p] = tu;
    out[p]  = 0.f;   // zero d_out (poisoned by harness); CAS claims rely on this

    // block-reduce per-batch maxima (of squares)
    float bm = mc, tm = tu;
    for (int o = 16; o; o >>= 1) {
        bm = fmaxf(bm, __shfl_xor_sync(0xffffffffu, bm, o));
        tm = fmaxf(tm, __shfl_xor_sync(0xffffffffu, tm, o));
    }
    if ((tid & 31) == 0) { red1[tid >> 5] = bm; red2[tid >> 5] = tm; }
    __syncthreads();
    if (tid < 32) {
        bm = red1[tid]; tm = red2[tid];
        for (int o = 16; o; o >>= 1) {
            bm = fmaxf(bm, __shfl_xor_sync(0xffffffffu, bm, o));
            tm = fmaxf(tm, __shfl_xor_sync(0xffffffffu, tm, o));
        }
        if (tid == 0) {
            atomicMax(&g_bmax[bb],  __float_as_uint(bm));
            atomicMax(&g_tumax[bb], __float_as_uint(tm));
        }
    }
}

// ---------------- K1.5: per-batch squared thresholds (16 sqrts total) -------------
__global__ void k_thresh() {
    __shared__ float s_hi;
    int t = threadIdx.x;
    if (t == 0) {
        float tmax = 0.f;
#pragma unroll
        for (int i = 0; i < NBATCH; i++) {
            float bm2 = __uint_as_float(g_bmax[i]);
            float tm2 = __uint_as_float(g_tumax[i]);
            if (bm2 > 0.f) tmax = fmaxf(tmax, sqrtf(tm2) / sqrtf(bm2));
        }
        s_hi = tmax * HIGH_T_C;
    }
    __syncthreads();
    if (t < NBATCH) {
        float bm = sqrtf(__uint_as_float(g_bmax[t]));
        float lo = LOW_T_C * bm, hi = s_hi * bm;
        g_lo2[t] = lo * lo;
        g_hi2[t] = hi * hi;
    }
}

// ---------------- bounded DFS expansion (claim via CAS; no div, no sqrt) ----------
__device__ __forceinline__ void expand_from(unsigned seed, float* out,
                                            float lo2, float hi2,
                                            int qidx, int maxpops) {
    unsigned stk[96];
    int sp = 0, pops = 0;
    unsigned cur = seed;
    const unsigned base = cur & ~0xFFFFFu;
    while (true) {
        int y = (cur >> 10) & 1023;
        int x = cur & 1023;
#pragma unroll
        for (int d = 0; d < 8; d++) {
            int ny = y + c_dy[d], nx = x + c_dx[d];
            if ((unsigned)ny < IMG_H && (unsigned)nx < IMG_W) {
                unsigned n = base | ((unsigned)ny << 10) | (unsigned)nx;
                float t = __ldg(&g_tu[n]);
                if (t < hi2 && t >= lo2) {        // weak pixel
                    unsigned old = atomicCAS((unsigned*)&out[n], 0u, STRONG_BITS);
                    if (old == 0u) {
                        if (sp < 96) stk[sp++] = n;
                        else {
                            unsigned pos = atomicAdd(&g_ovfn[qidx], 1u);
                            if (pos < OVF_CAP) g_ovfq[qidx][pos] = n;
                        }
                    }
                }
            }
        }
        if (sp == 0) break;
        if (++pops > maxpops) {  // hand remainder back for rebalancing
            while (sp > 0) {
                unsigned v = stk[--sp];
                unsigned pos = atomicAdd(&g_ovfn[qidx], 1u);
                if (pos < OVF_CAP) g_ovfq[qidx][pos] = v;
            }
            break;
        }
        cur = stk[--sp];
    }
}

// ---------------- K2: strong markers + first-wave weak claims -----------------------
// Strong pixels: plain out=255, NO queue push (R3's bug: ~3-4M seeds overflowed the queue).
// Expansion roots: WEAK pixels with a strong-VALUED neighbor (pure g_tu compares).
// These are uniformly spread over the image -> natural load balance; spill is tiny.
__global__ __launch_bounds__(256) void k_seed(float* __restrict__ out) {
    const unsigned stride = gridDim.x * blockDim.x;
    const float4* tu4 = (const float4*)g_tu;
    for (unsigned q = blockIdx.x * blockDim.x + threadIdx.x; q < NPIX / 4; q += stride) {
        float4 v = __ldg(&tu4[q]);
        unsigned p0 = q * 4;
        int bb = p0 >> 20;                 // 4 consecutive pixels share a batch
        float hi2 = g_hi2[bb], lo2 = g_lo2[bb];
        // quick reject: all 4 below lo2 (most of the image)
        if (fmaxf(fmaxf(v.x, v.y), fmaxf(v.z, v.w)) < lo2) continue;
#pragma unroll
        for (int j = 0; j < 4; j++) {
            float vv = (j == 0) ? v.x : (j == 1) ? v.y : (j == 2) ? v.z : v.w;
            unsigned p = p0 + j;
            if (vv >= hi2) {
                out[p] = 255.0f;           // strong: mark, never queued
            } else if (vv >= lo2) {
                // weak: root iff some neighbor is strong by value
                int y = (p >> 10) & 1023, x = p & 1023;
                unsigned base = p & ~0xFFFFFu;
                bool root = false;
#pragma unroll
                for (int d = 0; d < 8; d++) {
                    int ny = y + c_dy[d], nx = x + c_dx[d];
                    if ((unsigned)ny < IMG_H && (unsigned)nx < IMG_W) {
                        if (__ldg(&g_tu[base | ((unsigned)ny << 10) | (unsigned)nx]) >= hi2)
                            root = true;
                    }
                }
                if (root) {
                    unsigned old = atomicCAS((unsigned*)&out[p], 0u, STRONG_BITS);
                    if (old == 0u) expand_from(p, out, lo2, hi2, 0, 48);
                }
            }
        }
    }
}

// ---------------- K3: persistent drain of spill queue (grid barrier) --------------
__device__ __forceinline__ void gsync() {
    __syncthreads();
    if (threadIdx.x == 0) {
        unsigned gen = atomicAdd(&g_bar_gen, 0u);
        __threadfence();
        if (atomicAdd(&g_bar_cnt, 1u) == gridDim.x - 1) {
            atomicExch(&g_bar_cnt, 0u);
            __threadfence();
            atomicAdd(&g_bar_gen, 1u);
        } else {
            while (atomicAdd(&g_bar_gen, 0u) == gen) __nanosleep(100);
        }
        __threadfence();
    }
    __syncthreads();
}

__global__ __launch_bounds__(256, 2) void k_drain(float* __restrict__ out) {
    int curq = 0;
    while (true) {
        unsigned n = atomicAdd(&g_ovfn[curq], 0u);
        if (n == 0u) break;
        if (n > OVF_CAP) n = OVF_CAP;
        const unsigned stride = gridDim.x * blockDim.x;
        for (unsigned i = blockIdx.x * blockDim.x + threadIdx.x; i < n; i += stride) {
            unsigned p = __ldcg(&g_ovfq[curq][i]);
            int bb = p >> 20;
            expand_from(p, out, g_lo2[bb], g_hi2[bb], curq ^ 1, 64);
        }
        gsync();
        if (blockIdx.x == 0 && threadIdx.x == 0) atomicExch(&g_ovfn[curq], 0u);
        gsync();
        curq ^= 1;
    }
}

// ---------------- launch ----------------
extern "C" void kernel_launch(void* const* d_in, const int* in_sizes, int n_in,
                              void* d_out, int out_size) {
    const float* img = (const float*)d_in[0];
    float* out = (float*)d_out;
    (void)in_sizes; (void)n_in; (void)out_size;

    k_init<<<1, 32>>>();
    dim3 b1(32, 32), g1(IMG_W / 32, IMG_H / 32, NBATCH);
    k_front<<<g1, b1>>>(img, out);
    k_thresh<<<1, 32>>>();
    k_seed<<<2048, 256>>>(out);
    k_drain<<<296, 256>>>(out);   // 2 blocks/SM guaranteed resident -> grid barrier safe
}

// round 5
// speedup vs baseline: 2.1235x; 1.6502x over previous
#include <cuda_runtime.h>

#define IMG_H 1024
#define IMG_W 1024
#define NBATCH 16
#define NPIX (NBATCH * IMG_H * IMG_W)
#define OVF_CAP (1u << 23)
#define FULLM 0xffffffffu
#define M34 ((1ull << 34) - 1ull)

// ---------------- scratch (static device globals; no allocation) ----------------
__device__ float    g_tu[NPIX];          // SQUARED NMS-surviving magnitude (thin^2, unnormalized)
__device__ unsigned g_bmax[NBATCH];      // per-batch max mag^2 (float bits)
__device__ unsigned g_tumax[NBATCH];     // per-batch max thin^2 (float bits)
__device__ float    g_lo2[NBATCH];       // (LOW_T * bmax)^2
__device__ float    g_hi2[NBATCH];       // (hi * bmax)^2
__device__ unsigned g_ovfn[2];           // work queue counts (ping-pong)
__device__ unsigned g_ovfq[2][OVF_CAP];  // work queues
__device__ unsigned g_bar_cnt;           // grid barrier
__device__ unsigned g_bar_gen;

__constant__ int c_dy[8] = {0, 1, 1, 1, 0, -1, -1, -1};
__constant__ int c_dx[8] = {1, 1, 0, -1, -1, -1, 0, 1};

#define GW0 0.13533528323661270f   // exp(-2)
#define GW1 0.60653065971263342f   // exp(-0.5)
#define T1C 0.41421356237309503f   // tan(22.5 deg)
#define T2C 2.41421356237309510f   // tan(67.5 deg)
#define LOW_T_C 0.00392f
#define HIGH_T_C 0.15f
#define STRONG_BITS 0x437F0000u    // 255.0f

// ---------------- K0: reset scalars ----------------
__global__ void k_init() {
    int t = threadIdx.x;
    if (t < NBATCH) { g_bmax[t] = 0u; g_tumax[t] = 0u; }
    if (t < 2) g_ovfn[t] = 0u;
    if (t == 0) { g_bar_cnt = 0u; g_bar_gen = 0u; }
}

// ---------------- K1: fused blur + sobel + mag^2 + NMS (+ batch maxima) ----------
__global__ __launch_bounds__(1024) void k_front(const float* __restrict__ img) {
    __shared__ float sA[40 * 40];   // img tile, later S (blurred, stride 36)
    __shared__ float sB[40 * 36];   // H (h-blur), later mag^2 (stride 34)
    __shared__ float red1[32], red2[32];

    const int bb  = blockIdx.z;
    const int gy0 = blockIdx.y << 5, gx0 = blockIdx.x << 5;
    const int tx = threadIdx.x, ty = threadIdx.y;
    const int tid = (ty << 5) | tx;
    const float* im = img + bb * (IMG_H * IMG_W);

    for (int i = tid; i < 1600; i += 1024) {
        int ay = i / 40, ax = i - ay * 40;
        int gy = gy0 - 4 + ay, gx = gx0 - 4 + ax;
        float v = 0.f;
        if ((unsigned)gy < IMG_H && (unsigned)gx < IMG_W) v = __ldg(&im[gy * IMG_W + gx]);
        sA[i] = v;
    }
    __syncthreads();

    for (int i = tid; i < 1440; i += 1024) {
        int hy = i / 36, hx = i - hy * 36;
        const float* r = &sA[hy * 40 + hx];
        sB[i] = GW0 * r[0] + GW1 * r[1] + r[2] + GW1 * r[3] + GW0 * r[4];
    }
    __syncthreads();

    for (int i = tid; i < 1296; i += 1024) {
        int sy = i / 36, sx = i - sy * 36;
        const float* r = &sB[sy * 36 + sx];
        float v = GW0 * r[0] + GW1 * r[36] + r[72] + GW1 * r[108] + GW0 * r[144];
        int gy = gy0 - 2 + sy, gx = gx0 - 2 + sx;
        if ((unsigned)gy >= IMG_H || (unsigned)gx >= IMG_W) v = 0.f;
        sA[sy * 36 + sx] = v;
    }
    __syncthreads();

    for (int i = tid; i < 1156; i += 1024) {
        int my = i / 34, mx = i - my * 34;
        float m = 0.f;
        int gy = gy0 - 1 + my, gx = gx0 - 1 + mx;
        if ((unsigned)gy < IMG_H && (unsigned)gx < IMG_W) {
            const float* s = &sA[my * 36 + mx];
            float s00 = s[0],  s01 = s[1],  s02 = s[2];
            float s10 = s[36],              s12 = s[38];
            float s20 = s[72], s21 = s[73], s22 = s[74];
            float gxv = (s00 - s02) + 2.f * (s10 - s12) + (s20 - s22);
            float gyv = (s00 + 2.f * s01 + s02) - (s20 + 2.f * s21 + s22);
            m = gxv * gxv + gyv * gyv;           // squared magnitude — no sqrt
        }
        sB[my * 34 + mx] = m;
    }
    __syncthreads();

    const float* s = &sA[(ty + 1) * 36 + (tx + 1)];
    float s00 = s[0],  s01 = s[1],  s02 = s[2];
    float s10 = s[36],              s12 = s[38];
    float s20 = s[72], s21 = s[73], s22 = s[74];
    float Ix = (s00 - s02) + 2.f * (s10 - s12) + (s20 - s22);
    float Iy = (s00 + 2.f * s01 + s02) - (s20 + 2.f * s21 + s22);
    float mc = sB[(ty + 1) * 34 + (tx + 1)];

    float axv = fabsf(Ix), ayv = fabsf(Iy);
    int k;
    if (ayv <= T1C * axv)       k = (Ix >= 0.f) ? 4 : 0;
    else if (ayv >= T2C * axv)  k = (Iy > 0.f) ? 6 : 2;
    else                        k = (Iy > 0.f) ? ((Ix > 0.f) ? 5 : 7)
                                               : ((Ix > 0.f) ? 3 : 1);
    int dy = c_dy[k], dx = c_dx[k];
    float mp = sB[(ty + 1 + dy) * 34 + (tx + 1 + dx)];
    float mn = sB[(ty + 1 - dy) * 34 + (tx + 1 - dx)];
    float tu = (mc > mp && mc > mn) ? mc : 0.f;   // NMS on squares (sqrt monotone)

    unsigned p = ((unsigned)bb << 20) | ((unsigned)(gy0 + ty) << 10) | (unsigned)(gx0 + tx);
    g_tu[p] = tu;

    float bm = mc, tm = tu;
    for (int o = 16; o; o >>= 1) {
        bm = fmaxf(bm, __shfl_xor_sync(FULLM, bm, o));
        tm = fmaxf(tm, __shfl_xor_sync(FULLM, tm, o));
    }
    if ((tid & 31) == 0) { red1[tid >> 5] = bm; red2[tid >> 5] = tm; }
    __syncthreads();
    if (tid < 32) {
        bm = red1[tid]; tm = red2[tid];
        for (int o = 16; o; o >>= 1) {
            bm = fmaxf(bm, __shfl_xor_sync(FULLM, bm, o));
            tm = fmaxf(tm, __shfl_xor_sync(FULLM, tm, o));
        }
        if (tid == 0) {
            atomicMax(&g_bmax[bb],  __float_as_uint(bm));
            atomicMax(&g_tumax[bb], __float_as_uint(tm));
        }
    }
}

// ---------------- K1.5: per-batch squared thresholds (16 sqrts total) -------------
__global__ void k_thresh() {
    __shared__ float s_hi;
    int t = threadIdx.x;
    if (t == 0) {
        float tmax = 0.f;
#pragma unroll
        for (int i = 0; i < NBATCH; i++) {
            float bm2 = __uint_as_float(g_bmax[i]);
            float tm2 = __uint_as_float(g_tumax[i]);
            if (bm2 > 0.f) tmax = fmaxf(tmax, sqrtf(tm2) / sqrtf(bm2));
        }
        s_hi = tmax * HIGH_T_C;
    }
    __syncthreads();
    if (t < NBATCH) {
        float bm = sqrtf(__uint_as_float(g_bmax[t]));
        float lo = LOW_T_C * bm, hi = s_hi * bm;
        g_lo2[t] = lo * lo;
        g_hi2[t] = hi * hi;
    }
}

// ---------------- K2: warp-bitboard tile hysteresis --------------------------------
// One warp per 32x32 tile (+1px halo). Lane L owns row L as a 34-bit mask
// (bit c = col gx0-1+c). In-tile promotion: s |= w & dilate8(s), 64 px/instr,
// vertical neighbors via shfl, halo rows broadcast. Writes the full tile to out
// (coalesced). Promoted border pixels with an out-of-tile weak-by-value neighbor
// are queued for the global CAS-DFS drain.
__global__ __launch_bounds__(256) void k_seed(float* __restrict__ out) {
    const int lane = threadIdx.x & 31;
    const int tileId = blockIdx.x * 8 + (threadIdx.x >> 5);   // 16384 tiles
    const int bb = tileId >> 10;
    const int t  = tileId & 1023;
    const int gy0 = (t >> 5) << 5, gx0 = (t & 31) << 5;
    const float* tu = g_tu + (bb << 20);
    const float hi2 = g_hi2[bb], lo2 = g_lo2[bb];

    unsigned long long sm = 0, wm = 0;           // own-row initial strong/weak
    unsigned long long ht_s = 0, ht_w = 0;       // halo-top row (uniform)
    unsigned long long hb_s = 0, hb_w = 0;       // halo-bottom row (uniform)

    // classify 34 rows
    for (int r = 0; r < 34; r++) {
        int gy = gy0 - 1 + r;
        unsigned long long rs = 0, rw = 0;
        float v = 0.f, v2 = 0.f;
        if ((unsigned)gy < IMG_H) {
            int gx = gx0 - 1 + lane;
            if ((unsigned)gx < IMG_W) v = __ldg(&tu[(gy << 10) + gx]);
            int gx2 = gx0 + 31 + lane;
            if (lane < 2 && (unsigned)gx2 < IMG_W) v2 = __ldg(&tu[(gy << 10) + gx2]);
        }
        unsigned bs  = __ballot_sync(FULLM, v >= hi2);
        unsigned bw  = __ballot_sync(FULLM, v >= lo2 && v < hi2);
        unsigned bs2 = __ballot_sync(FULLM, lane < 2 && v2 >= hi2);
        unsigned bw2 = __ballot_sync(FULLM, lane < 2 && v2 >= lo2 && v2 < hi2);
        rs = (unsigned long long)bs | ((unsigned long long)(bs2 & 3u) << 32);
        rw = (unsigned long long)bw | ((unsigned long long)(bw2 & 3u) << 32);
        if (r == 0)        { ht_s = rs; ht_w = rw; }
        else if (r == 33)  { hb_s = rs; hb_w = rw; }
        else if (lane == r - 1) { sm = rs; wm = rw; }
    }

    // fixpoint propagation
    unsigned long long s = sm, hts = ht_s, hbs = hb_s;
    while (true) {
        unsigned long long up = __shfl_up_sync(FULLM, s, 1);
        if (lane == 0)  up = hts;
        unsigned long long dn = __shfl_down_sync(FULLM, s, 1);
        if (lane == 31) dn = hbs;
        unsigned long long dil = (s << 1) | (s >> 1)
                               | up | (up << 1) | (up >> 1)
                               | dn | (dn << 1) | (dn >> 1);
        unsigned long long ns = s | (wm & dil & M34);
        unsigned long long row0  = __shfl_sync(FULLM, s, 0);
        unsigned long long row31 = __shfl_sync(FULLM, s, 31);
        unsigned long long nht = hts | (ht_w & ((hts << 1) | (hts >> 1) | row0  | (row0 << 1)  | (row0 >> 1))  & M34);
        unsigned long long nhb = hbs | (hb_w & ((hbs << 1) | (hbs >> 1) | row31 | (row31 << 1) | (row31 >> 1)) & M34);
        bool ch = (ns != s) || (nht != hts) || (nhb != hbs);
        s = ns; hts = nht; hbs = nhb;
        if (!__any_sync(FULLM, ch)) break;
    }

    // coalesced tile write: 255 where final-strong, else 0
    const unsigned obase = ((unsigned)bb << 20) + ((unsigned)gy0 << 10) + (unsigned)gx0;
#pragma unroll 4
    for (int r = 0; r < 32; r++) {
        unsigned long long m = __shfl_sync(FULLM, s, r);
        out[obase + ((unsigned)r << 10) + lane] = ((m >> (lane + 1)) & 1ull) ? 255.0f : 0.0f;
    }

    // queue: promoted interior pixels with an out-of-tile weak-by-value neighbor
    unsigned long long prom = s & ~sm;
    unsigned long long wup = __shfl_up_sync(FULLM, wm, 1);
    if (lane == 0)  wup = ht_w;
    unsigned long long wdn = __shfl_down_sync(FULLM, wm, 1);
    if (lane == 31) wdn = hb_w;
    unsigned long long wvert = wup | wm | wdn;
    unsigned long long oow = 0;
    if (wvert & 1ull)            oow |= 2ull;            // left halo col -> bit1
    if ((wvert >> 33) & 1ull)    oow |= (1ull << 32);    // right halo col -> bit32
    if (lane == 0)  oow |= (ht_w | (ht_w << 1) | (ht_w >> 1));
    if (lane == 31) oow |= (hb_w | (hb_w << 1) | (hb_w >> 1));
    unsigned long long push = prom & oow & 0x1FFFFFFFEull;   // interior bits 1..32
    while (push) {
        int c = __ffsll((long long)push) - 1;
        push &= push - 1;
        unsigned p = ((unsigned)bb << 20) | ((unsigned)(gy0 + lane) << 10) | (unsigned)(gx0 + c - 1);
        unsigned pos = atomicAdd(&g_ovfn[0], 1u);
        if (pos < OVF_CAP) g_ovfq[0][pos] = p;
    }
}

// ---------------- bounded DFS expansion (claim via CAS) ---------------------------
__device__ __forceinline__ void expand_from(unsigned seed, float* out,
                                            float lo2, float hi2,
                                            int qidx, int maxpops) {
    unsigned stk[96];
    int sp = 0, pops = 0;
    unsigned cur = seed;
    const unsigned base = cur & ~0xFFFFFu;
    while (true) {
        int y = (cur >> 10) & 1023;
        int x = cur & 1023;
#pragma unroll
        for (int d = 0; d < 8; d++) {
            int ny = y + c_dy[d], nx = x + c_dx[d];
            if ((unsigned)ny < IMG_H && (unsigned)nx < IMG_W) {
                unsigned n = base | ((unsigned)ny << 10) | (unsigned)nx;
                float t = __ldg(&g_tu[n]);
                if (t < hi2 && t >= lo2) {        // weak pixel
                    unsigned old = atomicCAS((unsigned*)&out[n], 0u, STRONG_BITS);
                    if (old == 0u) {
                        if (sp < 96) stk[sp++] = n;
                        else {
                            unsigned pos = atomicAdd(&g_ovfn[qidx], 1u);
                            if (pos < OVF_CAP) g_ovfq[qidx][pos] = n;
                        }
                    }
                }
            }
        }
        if (sp == 0) break;
        if (++pops > maxpops) {
            while (sp > 0) {
                unsigned v = stk[--sp];
                unsigned pos = atomicAdd(&g_ovfn[qidx], 1u);
                if (pos < OVF_CAP) g_ovfq[qidx][pos] = v;
            }
            break;
        }
        cur = stk[--sp];
    }
}

// ---------------- K3: persistent drain of cross-tile queue (grid barrier) ---------
__device__ __forceinline__ void gsync() {
    __syncthreads();
    if (threadIdx.x == 0) {
        unsigned gen = atomicAdd(&g_bar_gen, 0u);
        __threadfence();
        if (atomicAdd(&g_bar_cnt, 1u) == gridDim.x - 1) {
            atomicExch(&g_bar_cnt, 0u);
            __threadfence();
            atomicAdd(&g_bar_gen, 1u);
        } else {
            while (atomicAdd(&g_bar_gen, 0u) == gen) __nanosleep(100);
        }
        __threadfence();
    }
    __syncthreads();
}

__global__ __launch_bounds__(256, 2) void k_drain(float* __restrict__ out) {
    int curq = 0;
    while (true) {
        unsigned n = atomicAdd(&g_ovfn[curq], 0u);
        if (n == 0u) break;
        if (n > OVF_CAP) n = OVF_CAP;
        const unsigned stride = gridDim.x * blockDim.x;
        for (unsigned i = blockIdx.x * blockDim.x + threadIdx.x; i < n; i += stride) {
            unsigned p = __ldcg(&g_ovfq[curq][i]);
            int bb = p >> 20;
            expand_from(p, out, g_lo2[bb], g_hi2[bb], curq ^ 1, 64);
        }
        gsync();
        if (blockIdx.x == 0 && threadIdx.x == 0) atomicExch(&g_ovfn[curq], 0u);
        gsync();
        curq ^= 1;
    }
}

// ---------------- launch ----------------
extern "C" void kernel_launch(void* const* d_in, const int* in_sizes, int n_in,
                              void* d_out, int out_size) {
    const float* img = (const float*)d_in[0];
    float* out = (float*)d_out;
    (void)in_sizes; (void)n_in; (void)out_size;

    k_init<<<1, 32>>>();
    dim3 b1(32, 32), g1(IMG_W / 32, IMG_H / 32, NBATCH);
    k_front<<<g1, b1>>>(img);
    k_thresh<<<1, 32>>>();
    k_seed<<<2048, 256>>>(out);     // 8 warps/block, 1 warp = 1 tile (16384 tiles)
    k_drain<<<296, 256>>>(out);     // 2 blocks/SM resident -> grid barrier safe
}

// round 6
// speedup vs baseline: 2.9237x; 1.3768x over previous
#include <cuda_runtime.h>

#define IMG_H 1024
#define IMG_W 1024
#define NBATCH 16
#define NPIX (NBATCH * IMG_H * IMG_W)
#define OVF_CAP (1u << 23)
#define FULLM 0xffffffffu
#define M34 ((1ull << 34) - 1ull)

// k_front tiling: 64x64 output, +/-4 halo
#define TS 64
#define TIN 72      // input tile  (TS+8)
#define THB 68      // h-blurred   (TS+4)
#define TMG 66      // mag^2       (TS+2)

// ---------------- scratch (static device globals; no allocation) ----------------
__device__ float    g_tu[NPIX];          // SQUARED NMS-surviving magnitude
__device__ unsigned g_bmax[NBATCH];      // per-batch max mag^2 (float bits)
__device__ unsigned g_tumax[NBATCH];     // per-batch max thin^2 (float bits)
__device__ float    g_lo2[NBATCH];
__device__ float    g_hi2[NBATCH];
__device__ unsigned g_ovfn[2];
__device__ unsigned g_ovfq[2][OVF_CAP];
__device__ unsigned g_bar_cnt;
__device__ unsigned g_bar_gen;

__constant__ int c_dy[8] = {0, 1, 1, 1, 0, -1, -1, -1};
__constant__ int c_dx[8] = {1, 1, 0, -1, -1, -1, 0, 1};

#define GW0 0.13533528323661270f
#define GW1 0.60653065971263342f
#define T1C 0.41421356237309503f
#define T2C 2.41421356237309510f
#define LOW_T_C 0.00392f
#define HIGH_T_C 0.15f
#define STRONG_BITS 0x437F0000u

// ---------------- K0 ----------------
__global__ void k_init() {
    int t = threadIdx.x;
    if (t < NBATCH) { g_bmax[t] = 0u; g_tumax[t] = 0u; }
    if (t < 2) g_ovfn[t] = 0u;
    if (t == 0) { g_bar_cnt = 0u; g_bar_gen = 0u; }
}

// ---------------- K1: fused blur + sobel + mag^2 + sector + NMS (+ zero out) ------
__global__ __launch_bounds__(1024) void k_front(const float* __restrict__ img,
                                                float* __restrict__ out) {
    __shared__ float sA[TIN * TIN];          // img tile; later S (stride THB)
    __shared__ float sB[TIN * THB];          // h-blur;   later mag^2 (stride TMG)
    __shared__ unsigned char sK[TS * TS];    // sector index per interior pixel
    __shared__ float red1[32], red2[32];

    const int bb  = blockIdx.z;
    const int gy0 = blockIdx.y * TS, gx0 = blockIdx.x * TS;
    const int tid = threadIdx.x;
    const float* im = img + bb * (IMG_H * IMG_W);

    // load 72x72, zero-padded (origin gy0-4, gx0-4)
    for (int i = tid; i < TIN * TIN; i += 1024) {
        int ay = i / TIN, ax = i - ay * TIN;
        int gy = gy0 - 4 + ay, gx = gx0 - 4 + ax;
        float v = 0.f;
        if ((unsigned)gy < IMG_H && (unsigned)gx < IMG_W) v = __ldg(&im[gy * IMG_W + gx]);
        sA[i] = v;
    }
    __syncthreads();

    // horizontal blur: 72 rows x 68 cols -> sB
    for (int i = tid; i < TIN * THB; i += 1024) {
        int hy = i / THB, hx = i - hy * THB;
        const float* r = &sA[hy * TIN + hx];
        sB[i] = GW0 * r[0] + GW1 * r[1] + r[2] + GW1 * r[3] + GW0 * r[4];
    }
    __syncthreads();

    // vertical blur: 68x68 -> sA (stride 68); zero outside image (sobel zero-pad)
    for (int i = tid; i < THB * THB; i += 1024) {
        int sy = i / THB, sx = i - sy * THB;
        const float* r = &sB[sy * THB + sx];
        float v = GW0 * r[0] + GW1 * r[THB] + r[2 * THB] + GW1 * r[3 * THB] + GW0 * r[4 * THB];
        int gy = gy0 - 2 + sy, gx = gx0 - 2 + sx;
        if ((unsigned)gy >= IMG_H || (unsigned)gx >= IMG_W) v = 0.f;
        sA[sy * THB + sx] = v;
    }
    __syncthreads();

    // mag^2 on 66x66 -> sB (stride 66); sector for interior while Ix/Iy are live
    for (int i = tid; i < TMG * TMG; i += 1024) {
        int my = i / TMG, mx = i - my * TMG;
        float m = 0.f, Ix = 0.f, Iy = 0.f;
        int gy = gy0 - 1 + my, gx = gx0 - 1 + mx;
        if ((unsigned)gy < IMG_H && (unsigned)gx < IMG_W) {
            const float* s = &sA[my * THB + mx];
            float s00 = s[0],       s01 = s[1],           s02 = s[2];
            float s10 = s[THB],                           s12 = s[THB + 2];
            float s20 = s[2 * THB], s21 = s[2 * THB + 1], s22 = s[2 * THB + 2];
            Ix = (s00 - s02) + 2.f * (s10 - s12) + (s20 - s22);
            Iy = (s00 + 2.f * s01 + s02) - (s20 + 2.f * s21 + s22);
            m = Ix * Ix + Iy * Iy;
        }
        sB[my * TMG + mx] = m;
        if ((unsigned)(my - 1) < TS && (unsigned)(mx - 1) < TS) {
            // k == rint((atan2(Iy,Ix)*180/pi + 180)/45) % 8 via slope compares
            float axv = fabsf(Ix), ayv = fabsf(Iy);
            int k;
            if (ayv <= T1C * axv)       k = (Ix >= 0.f) ? 4 : 0;
            else if (ayv >= T2C * axv)  k = (Iy > 0.f) ? 6 : 2;
            else                        k = (Iy > 0.f) ? ((Ix > 0.f) ? 5 : 7)
                                                       : ((Ix > 0.f) ? 3 : 1);
            sK[(my - 1) * TS + (mx - 1)] = (unsigned char)k;
        }
    }
    __syncthreads();

    // per-pixel NMS (4 px/thread), write g_tu + zero out, reduce batch maxima
    const int tx = tid & 63, tyq = tid >> 6;      // 64 x 16 layout
    float bm = 0.f, tm = 0.f;
#pragma unroll
    for (int j = 0; j < 4; j++) {
        int oy = tyq + j * 16, ox = tx;
        float mc = sB[(oy + 1) * TMG + (ox + 1)];
        int k = sK[oy * TS + ox];
        int dy = c_dy[k], dx = c_dx[k];
        float mp = sB[(oy + 1 + dy) * TMG + (ox + 1 + dx)];
        float mn = sB[(oy + 1 - dy) * TMG + (ox + 1 - dx)];
        float tu = (mc > mp && mc > mn) ? mc : 0.f;
        unsigned p = ((unsigned)bb << 20) | ((unsigned)(gy0 + oy) << 10) | (unsigned)(gx0 + ox);
        g_tu[p] = tu;
        out[p]  = 0.f;                            // pre-zero: k_seed writes 255s only
        bm = fmaxf(bm, mc); tm = fmaxf(tm, tu);
    }
    for (int o = 16; o; o >>= 1) {
        bm = fmaxf(bm, __shfl_xor_sync(FULLM, bm, o));
        tm = fmaxf(tm, __shfl_xor_sync(FULLM, tm, o));
    }
    if ((tid & 31) == 0) { red1[tid >> 5] = bm; red2[tid >> 5] = tm; }
    __syncthreads();
    if (tid < 32) {
        bm = red1[tid]; tm = red2[tid];
        for (int o = 16; o; o >>= 1) {
            bm = fmaxf(bm, __shfl_xor_sync(FULLM, bm, o));
            tm = fmaxf(tm, __shfl_xor_sync(FULLM, tm, o));
        }
        if (tid == 0) {
            atomicMax(&g_bmax[bb],  __float_as_uint(bm));
            atomicMax(&g_tumax[bb], __float_as_uint(tm));
        }
    }
}

// ---------------- K1.5: per-batch squared thresholds ------------------------------
__global__ void k_thresh() {
    __shared__ float s_hi;
    int t = threadIdx.x;
    if (t == 0) {
        float tmax = 0.f;
#pragma unroll
        for (int i = 0; i < NBATCH; i++) {
            float bm2 = __uint_as_float(g_bmax[i]);
            float tm2 = __uint_as_float(g_tumax[i]);
            if (bm2 > 0.f) tmax = fmaxf(tmax, sqrtf(tm2) / sqrtf(bm2));
        }
        s_hi = tmax * HIGH_T_C;
    }
    __syncthreads();
    if (t < NBATCH) {
        float bm = sqrtf(__uint_as_float(g_bmax[t]));
        float lo = LOW_T_C * bm, hi = s_hi * bm;
        g_lo2[t] = lo * lo;
        g_hi2[t] = hi * hi;
    }
}

// ---------------- bounded DFS expansion (claim via CAS) ---------------------------
__device__ __forceinline__ void expand_from(unsigned seed, float* out,
                                            float lo2, float hi2,
                                            int qidx, int maxpops) {
    unsigned stk[96];
    int sp = 0, pops = 0;
    unsigned cur = seed;
    const unsigned base = cur & ~0xFFFFFu;
    while (true) {
        int y = (cur >> 10) & 1023;
        int x = cur & 1023;
#pragma unroll
        for (int d = 0; d < 8; d++) {
            int ny = y + c_dy[d], nx = x + c_dx[d];
            if ((unsigned)ny < IMG_H && (unsigned)nx < IMG_W) {
                unsigned n = base | ((unsigned)ny << 10) | (unsigned)nx;
                float t = __ldg(&g_tu[n]);
                if (t < hi2 && t >= lo2) {
                    unsigned old = atomicCAS((unsigned*)&out[n], 0u, STRONG_BITS);
                    if (old == 0u) {
                        if (sp < 96) stk[sp++] = n;
                        else {
                            unsigned pos = atomicAdd(&g_ovfn[qidx], 1u);
                            if (pos < OVF_CAP) g_ovfq[qidx][pos] = n;
                        }
                    }
                }
            }
        }
        if (sp == 0) break;
        if (++pops > maxpops) {
            while (sp > 0) {
                unsigned v = stk[--sp];
                unsigned pos = atomicAdd(&g_ovfn[qidx], 1u);
                if (pos < OVF_CAP) g_ovfq[qidx][pos] = v;
            }
            break;
        }
        cur = stk[--sp];
    }
}

// ---------------- K2: warp-bitboard tile hysteresis + inline cross-tile expansion --
__global__ __launch_bounds__(256) void k_seed(float* __restrict__ out) {
    const int lane = threadIdx.x & 31;
    const int tileId = blockIdx.x * 8 + (threadIdx.x >> 5);   // 16384 32x32 tiles
    const int bb = tileId >> 10;
    const int t  = tileId & 1023;
    const int gy0 = (t >> 5) << 5, gx0 = (t & 31) << 5;
    const float* tu = g_tu + (bb << 20);
    const float hi2 = g_hi2[bb], lo2 = g_lo2[bb];

    unsigned long long sm = 0, wm = 0;
    unsigned long long ht_s = 0, ht_w = 0;
    unsigned long long hb_s = 0, hb_w = 0;

    for (int r = 0; r < 34; r++) {
        int gy = gy0 - 1 + r;
        float v = 0.f, v2 = 0.f;
        if ((unsigned)gy < IMG_H) {
            int gx = gx0 - 1 + lane;
            if ((unsigned)gx < IMG_W) v = __ldg(&tu[(gy << 10) + gx]);
            int gx2 = gx0 + 31 + lane;
            if (lane < 2 && (unsigned)gx2 < IMG_W) v2 = __ldg(&tu[(gy << 10) + gx2]);
        }
        unsigned bs  = __ballot_sync(FULLM, v >= hi2);
        unsigned bw  = __ballot_sync(FULLM, v >= lo2 && v < hi2);
        unsigned bs2 = __ballot_sync(FULLM, lane < 2 && v2 >= hi2);
        unsigned bw2 = __ballot_sync(FULLM, lane < 2 && v2 >= lo2 && v2 < hi2);
        unsigned long long rs = (unsigned long long)bs | ((unsigned long long)(bs2 & 3u) << 32);
        unsigned long long rw = (unsigned long long)bw | ((unsigned long long)(bw2 & 3u) << 32);
        if (r == 0)        { ht_s = rs; ht_w = rw; }
        else if (r == 33)  { hb_s = rs; hb_w = rw; }
        else if (lane == r - 1) { sm = rs; wm = rw; }
    }

    // fixpoint: s |= w & dilate8(s)
    unsigned long long s = sm, hts = ht_s, hbs = hb_s;
    while (true) {
        unsigned long long up = __shfl_up_sync(FULLM, s, 1);
        if (lane == 0)  up = hts;
        unsigned long long dn = __shfl_down_sync(FULLM, s, 1);
        if (lane == 31) dn = hbs;
        unsigned long long dil = (s << 1) | (s >> 1)
                               | up | (up << 1) | (up >> 1)
                               | dn | (dn << 1) | (dn >> 1);
        unsigned long long ns = s | (wm & dil & M34);
        unsigned long long row0  = __shfl_sync(FULLM, s, 0);
        unsigned long long row31 = __shfl_sync(FULLM, s, 31);
        unsigned long long nht = hts | (ht_w & ((hts << 1) | (hts >> 1) | row0  | (row0 << 1)  | (row0 >> 1))  & M34);
        unsigned long long nhb = hbs | (hb_w & ((hbs << 1) | (hbs >> 1) | row31 | (row31 << 1) | (row31 >> 1)) & M34);
        bool ch = (ns != s) || (nht != hts) || (nhb != hbs);
        s = ns; hts = nht; hbs = nhb;
        if (!__any_sync(FULLM, ch)) break;
    }

    // sparse coalesced 255 writes (out pre-zeroed by k_front; 255-only writes are
    // race-free against concurrent cross-tile CAS claims — all writers write 255)
    const unsigned obase = ((unsigned)bb << 20) + ((unsigned)gy0 << 10) + (unsigned)gx0;
#pragma unroll 4
    for (int r = 0; r < 32; r++) {
        unsigned long long m = __shfl_sync(FULLM, s, r);
        if ((m >> (lane + 1)) & 1ull)
            out[obase + ((unsigned)r << 10) + lane] = 255.0f;
    }

    // inline expansion from promoted interior pixels with out-of-tile weak neighbor
    unsigned long long prom = s & ~sm;
    unsigned long long wup = __shfl_up_sync(FULLM, wm, 1);
    if (lane == 0)  wup = ht_w;
    unsigned long long wdn = __shfl_down_sync(FULLM, wm, 1);
    if (lane == 31) wdn = hb_w;
    unsigned long long wvert = wup | wm | wdn;
    unsigned long long oow = 0;
    if (wvert & 1ull)            oow |= 2ull;
    if ((wvert >> 33) & 1ull)    oow |= (1ull << 32);
    if (lane == 0)  oow |= (ht_w | (ht_w << 1) | (ht_w >> 1));
    if (lane == 31) oow |= (hb_w | (hb_w << 1) | (hb_w >> 1));
    unsigned long long push = prom & oow & 0x1FFFFFFFEull;
    while (push) {
        int c = __ffsll((long long)push) - 1;
        push &= push - 1;
        unsigned p = ((unsigned)bb << 20) | ((unsigned)(gy0 + lane) << 10) | (unsigned)(gx0 + c - 1);
        expand_from(p, out, lo2, hi2, 0, 96);
    }
}

// ---------------- K3: persistent drain (backstop for spills) ----------------------
__device__ __forceinline__ void gsync() {
    __syncthreads();
    if (threadIdx.x == 0) {
        unsigned gen = atomicAdd(&g_bar_gen, 0u);
        __threadfence();
        if (atomicAdd(&g_bar_cnt, 1u) == gridDim.x - 1) {
            atomicExch(&g_bar_cnt, 0u);
            __threadfence();
            atomicAdd(&g_bar_gen, 1u);
        } else {
            while (atomicAdd(&g_bar_gen, 0u) == gen) __nanosleep(100);
        }
        __threadfence();
    }
    __syncthreads();
}

__global__ __launch_bounds__(256, 2) void k_drain(float* __restrict__ out) {
    int curq = 0;
    while (true) {
        unsigned n = atomicAdd(&g_ovfn[curq], 0u);
        if (n == 0u) break;
        if (n > OVF_CAP) n = OVF_CAP;
        const unsigned stride = gridDim.x * blockDim.x;
        for (unsigned i = blockIdx.x * blockDim.x + threadIdx.x; i < n; i += stride) {
            unsigned p = __ldcg(&g_ovfq[curq][i]);
            int bb = p >> 20;
            expand_from(p, out, g_lo2[bb], g_hi2[bb], curq ^ 1, 64);
        }
        gsync();
        if (blockIdx.x == 0 && threadIdx.x == 0) atomicExch(&g_ovfn[curq], 0u);
        gsync();
        curq ^= 1;
    }
}

// ---------------- launch ----------------
extern "C" void kernel_launch(void* const* d_in, const int* in_sizes, int n_in,
                              void* d_out, int out_size) {
    const float* img = (const float*)d_in[0];
    float* out = (float*)d_out;
    (void)in_sizes; (void)n_in; (void)out_size;

    k_init<<<1, 32>>>();
    dim3 b1(1024), g1(IMG_W / TS, IMG_H / TS, NBATCH);
    k_front<<<g1, b1>>>(img, out);
    k_thresh<<<1, 32>>>();
    k_seed<<<2048, 256>>>(out);
    k_drain<<<296, 256>>>(out);
}

// round 9
// speedup vs baseline: 3.0891x; 1.0566x over previous
#include <cuda_runtime.h>

#define IMG_H 1024
#define IMG_W 1024
#define NBATCH 16
#define NPIX (NBATCH * IMG_H * IMG_W)
#define OVF_CAP (1u << 23)
#define FULLM 0xffffffffu
#define M34 ((1ull << 34) - 1ull)

// k_front tiling: 64x64 output, +/-4 halo
#define TS 64
#define TIN 72      // input tile  (TS+8)
#define THB 68      // h-blurred   (TS+4)
#define TMG 66      // mag^2       (TS+2)

// ---------------- scratch (static device globals; no allocation) ----------------
__device__ float    g_tu[NPIX];          // SQUARED NMS-surviving magnitude
__device__ unsigned g_bmax[NBATCH];      // per-batch max mag^2 (float bits)
__device__ unsigned g_tumax[NBATCH];     // per-batch max thin^2 (float bits)
__device__ float    g_lo2[NBATCH];
__device__ float    g_hi2[NBATCH];
__device__ unsigned g_ovfn[2];
__device__ unsigned g_ovfq[2][OVF_CAP];
__device__ unsigned g_bar_cnt;
__device__ unsigned g_bar_gen;

__constant__ int c_dy[8] = {0, 1, 1, 1, 0, -1, -1, -1};
__constant__ int c_dx[8] = {1, 1, 0, -1, -1, -1, 0, 1};

#define GW0 0.13533528323661270f
#define GW1 0.60653065971263342f
#define T1C 0.41421356237309503f
#define T2C 2.41421356237309510f
#define LOW_T_C 0.00392f
#define HIGH_T_C 0.15f
#define STRONG_BITS 0x437F0000u

// ---------------- K0 ----------------
__global__ void k_init() {
    int t = threadIdx.x;
    if (t < NBATCH) { g_bmax[t] = 0u; g_tumax[t] = 0u; }
    if (t < 2) g_ovfn[t] = 0u;
    if (t == 0) { g_bar_cnt = 0u; g_bar_gen = 0u; }
}

// ---------------- K1 body: fused blur + sobel + mag^2 + sector + NMS --------------
// BORDER=false: block's 72x72 input window is fully inside the image -> no bounds.
template <bool BORDER>
__device__ __forceinline__ void front_body(const float* __restrict__ img,
                                           float* sA, float* sB, unsigned char* sK,
                                           float* red1, float* red2) {
    const int bb  = blockIdx.z;
    const int gy0 = blockIdx.y * TS, gx0 = blockIdx.x * TS;
    const int tid = threadIdx.x;
    const float* im = img + bb * (IMG_H * IMG_W);

    // load 72x72 (origin gy0-4, gx0-4)
    if (BORDER) {
        for (int i = tid; i < TIN * TIN; i += 1024) {
            int ay = i / TIN, ax = i - ay * TIN;
            int gy = gy0 - 4 + ay, gx = gx0 - 4 + ax;
            float v = 0.f;
            if ((unsigned)gy < IMG_H && (unsigned)gx < IMG_W) v = __ldg(&im[gy * IMG_W + gx]);
            sA[i] = v;
        }
    } else {
        const float* org = im + (gy0 - 4) * IMG_W + (gx0 - 4);
#pragma unroll
        for (int j = 0; j < 6; j++) {               // 6*1024 > 5184: last chunk guarded
            int i = tid + j * 1024;
            if (j < 5 || i < TIN * TIN) {
                int ay = i / TIN, ax = i - ay * TIN;
                sA[i] = __ldg(&org[ay * IMG_W + ax]);
            }
        }
    }
    __syncthreads();

    // horizontal blur: 72 rows x 68 cols -> sB (no image-bounds dependence)
    for (int i = tid; i < TIN * THB; i += 1024) {
        int hy = i / THB, hx = i - hy * THB;
        const float* r = &sA[hy * TIN + hx];
        sB[i] = GW0 * r[0] + GW1 * r[1] + r[2] + GW1 * r[3] + GW0 * r[4];
    }
    __syncthreads();

    // vertical blur: 68x68 -> sA (stride 68); zero outside image (sobel zero-pad)
    for (int i = tid; i < THB * THB; i += 1024) {
        int sy = i / THB, sx = i - sy * THB;
        const float* r = &sB[sy * THB + sx];
        float v = GW0 * r[0] + GW1 * r[THB] + r[2 * THB] + GW1 * r[3 * THB] + GW0 * r[4 * THB];
        if (BORDER) {
            int gy = gy0 - 2 + sy, gx = gx0 - 2 + sx;
            if ((unsigned)gy >= IMG_H || (unsigned)gx >= IMG_W) v = 0.f;
        }
        sA[sy * THB + sx] = v;
    }
    __syncthreads();

    // mag^2 on 66x66 -> sB (stride 66); sector for interior pixels while Ix/Iy live
    for (int i = tid; i < TMG * TMG; i += 1024) {
        int my = i / TMG, mx = i - my * TMG;
        const float* s = &sA[my * THB + mx];
        float s00 = s[0],       s01 = s[1],           s02 = s[2];
        float s10 = s[THB],                           s12 = s[THB + 2];
        float s20 = s[2 * THB], s21 = s[2 * THB + 1], s22 = s[2 * THB + 2];
        float Ix = (s00 - s02) + 2.f * (s10 - s12) + (s20 - s22);
        float Iy = (s00 + 2.f * s01 + s02) - (s20 + 2.f * s21 + s22);
        float m = Ix * Ix + Iy * Iy;
        if (BORDER) {
            int gy = gy0 - 1 + my, gx = gx0 - 1 + mx;
            if ((unsigned)gy >= IMG_H || (unsigned)gx >= IMG_W) { m = 0.f; Ix = 0.f; Iy = 0.f; }
        }
        sB[my * TMG + mx] = m;
        if ((unsigned)(my - 1) < TS && (unsigned)(mx - 1) < TS) {
            float axv = fabsf(Ix), ayv = fabsf(Iy);
            int k;
            if (ayv <= T1C * axv)       k = (Ix >= 0.f) ? 4 : 0;
            else if (ayv >= T2C * axv)  k = (Iy > 0.f) ? 6 : 2;
            else                        k = (Iy > 0.f) ? ((Ix > 0.f) ? 5 : 7)
                                                       : ((Ix > 0.f) ? 3 : 1);
            sK[(my - 1) * TS + (mx - 1)] = (unsigned char)k;
        }
    }
    __syncthreads();

    // per-pixel NMS (4 px/thread), write g_tu, reduce batch maxima
    const int tx = tid & 63, tyq = tid >> 6;      // 64 x 16 layout
    float bm = 0.f, tm = 0.f;
#pragma unroll
    for (int j = 0; j < 4; j++) {
        int oy = tyq + j * 16, ox = tx;
        float mc = sB[(oy + 1) * TMG + (ox + 1)];
        int k = sK[oy * TS + ox];
        int dy = c_dy[k], dx = c_dx[k];
        float mp = sB[(oy + 1 + dy) * TMG + (ox + 1 + dx)];
        float mn = sB[(oy + 1 - dy) * TMG + (ox + 1 - dx)];
        float tu = (mc > mp && mc > mn) ? mc : 0.f;
        unsigned p = ((unsigned)bb << 20) | ((unsigned)(gy0 + oy) << 10) | (unsigned)(gx0 + ox);
        g_tu[p] = tu;
        bm = fmaxf(bm, mc); tm = fmaxf(tm, tu);
    }
    for (int o = 16; o; o >>= 1) {
        bm = fmaxf(bm, __shfl_xor_sync(FULLM, bm, o));
        tm = fmaxf(tm, __shfl_xor_sync(FULLM, tm, o));
    }
    if ((tid & 31) == 0) { red1[tid >> 5] = bm; red2[tid >> 5] = tm; }
    __syncthreads();
    if (tid < 32) {
        bm = red1[tid]; tm = red2[tid];
        for (int o = 16; o; o >>= 1) {
            bm = fmaxf(bm, __shfl_xor_sync(FULLM, bm, o));
            tm = fmaxf(tm, __shfl_xor_sync(FULLM, tm, o));
        }
        if (tid == 0) {
            atomicMax(&g_bmax[bb],  __float_as_uint(bm));
            atomicMax(&g_tumax[bb], __float_as_uint(tm));
        }
    }
}

__global__ __launch_bounds__(1024) void k_front(const float* __restrict__ img) {
    __shared__ float sA[TIN * TIN];
    __shared__ float sB[TIN * THB];
    __shared__ unsigned char sK[TS * TS];
    __shared__ float red1[32], red2[32];
    bool border = (blockIdx.x == 0) | (blockIdx.x == gridDim.x - 1) |
                  (blockIdx.y == 0) | (blockIdx.y == gridDim.y - 1);
    if (border) front_body<true>(img, sA, sB, sK, red1, red2);
    else        front_body<false>(img, sA, sB, sK, red1, red2);
}

// ---------------- K1.5: per-batch squared thresholds ------------------------------
__global__ void k_thresh() {
    __shared__ float s_hi;
    int t = threadIdx.x;
    if (t == 0) {
        float tmax = 0.f;
#pragma unroll
        for (int i = 0; i < NBATCH; i++) {
            float bm2 = __uint_as_float(g_bmax[i]);
            float tm2 = __uint_as_float(g_tumax[i]);
            if (bm2 > 0.f) tmax = fmaxf(tmax, sqrtf(tm2) / sqrtf(bm2));
        }
        s_hi = tmax * HIGH_T_C;
    }
    __syncthreads();
    if (t < NBATCH) {
        float bm = sqrtf(__uint_as_float(g_bmax[t]));
        float lo = LOW_T_C * bm, hi = s_hi * bm;
        g_lo2[t] = lo * lo;
        g_hi2[t] = hi * hi;
    }
}

// ---------------- bounded DFS expansion (claim via CAS) ---------------------------
__device__ __forceinline__ void expand_from(unsigned seed, float* out,
                                            float lo2, float hi2,
                                            int qidx, int maxpops) {
    unsigned stk[96];
    int sp = 0, pops = 0;
    unsigned cur = seed;
    const unsigned base = cur & ~0xFFFFFu;
    while (true) {
        int y = (cur >> 10) & 1023;
        int x = cur & 1023;
#pragma unroll
        for (int d = 0; d < 8; d++) {
            int ny = y + c_dy[d], nx = x + c_dx[d];
            if ((unsigned)ny < IMG_H && (unsigned)nx < IMG_W) {
                unsigned n = base | ((unsigned)ny << 10) | (unsigned)nx;
                float t = __ldg(&g_tu[n]);
                if (t < hi2 && t >= lo2) {
                    unsigned old = atomicCAS((unsigned*)&out[n], 0u, STRONG_BITS);
                    if (old == 0u) {
                        if (sp < 96) stk[sp++] = n;
                        else {
                            unsigned pos = atomicAdd(&g_ovfn[qidx], 1u);
                            if (pos < OVF_CAP) g_ovfq[qidx][pos] = n;
                        }
                    }
                }
            }
        }
        if (sp == 0) break;
        if (++pops > maxpops) {
            while (sp > 0) {
                unsigned v = stk[--sp];
                unsigned pos = atomicAdd(&g_ovfn[qidx], 1u);
                if (pos < OVF_CAP) g_ovfq[qidx][pos] = v;
            }
            break;
        }
        cur = stk[--sp];
    }
}

// ---------------- K2: warp-bitboard tile hysteresis + inline cross-tile expansion --
__global__ __launch_bounds__(256) void k_seed(float* __restrict__ out) {
    const int lane = threadIdx.x & 31;
    const int tileId = blockIdx.x * 8 + (threadIdx.x >> 5);   // 16384 32x32 tiles
    const int bb = tileId >> 10;
    const int t  = tileId & 1023;
    const int gy0 = (t >> 5) << 5, gx0 = (t & 31) << 5;
    const float* tu = g_tu + (bb << 20);
    const float hi2 = g_hi2[bb], lo2 = g_lo2[bb];

    unsigned long long sm = 0, wm = 0;
    unsigned long long ht_s = 0, ht_w = 0;
    unsigned long long hb_s = 0, hb_w = 0;

    for (int r = 0; r < 34; r++) {
        int gy = gy0 - 1 + r;
        float v = 0.f, v2 = 0.f;
        if ((unsigned)gy < IMG_H) {
            int gx = gx0 - 1 + lane;
            if ((unsigned)gx < IMG_W) v = __ldg(&tu[(gy << 10) + gx]);
            int gx2 = gx0 + 31 + lane;
            if (lane < 2 && (unsigned)gx2 < IMG_W) v2 = __ldg(&tu[(gy << 10) + gx2]);
        }
        unsigned bs  = __ballot_sync(FULLM, v >= hi2);
        unsigned bw  = __ballot_sync(FULLM, v >= lo2 && v < hi2);
        unsigned bs2 = __ballot_sync(FULLM, lane < 2 && v2 >= hi2);
        unsigned bw2 = __ballot_sync(FULLM, lane < 2 && v2 >= lo2 && v2 < hi2);
        unsigned long long rs = (unsigned long long)bs | ((unsigned long long)(bs2 & 3u) << 32);
        unsigned long long rw = (unsigned long long)bw | ((unsigned long long)(bw2 & 3u) << 32);
        if (r == 0)        { ht_s = rs; ht_w = rw; }
        else if (r == 33)  { hb_s = rs; hb_w = rw; }
        else if (lane == r - 1) { sm = rs; wm = rw; }
    }

    // fixpoint: s |= w & dilate8(s)
    unsigned long long s = sm, hts = ht_s, hbs = hb_s;
    while (true) {
        unsigned long long up = __shfl_up_sync(FULLM, s, 1);
        if (lane == 0)  up = hts;
        unsigned long long dn = __shfl_down_sync(FULLM, s, 1);
        if (lane == 31) dn = hbs;
        unsigned long long dil = (s << 1) | (s >> 1)
                               | up | (up << 1) | (up >> 1)
                               | dn | (dn << 1) | (dn >> 1);
        unsigned long long ns = s | (wm & dil & M34);
        unsigned long long row0  = __shfl_sync(FULLM, s, 0);
        unsigned long long row31 = __shfl_sync(FULLM, s, 31);
        unsigned long long nht = hts | (ht_w & ((hts << 1) | (hts >> 1) | row0  | (row0 << 1)  | (row0 >> 1))  & M34);
        unsigned long long nhb = hbs | (hb_w & ((hbs << 1) | (hbs >> 1) | row31 | (row31 << 1) | (row31 >> 1)) & M34);
        bool ch = (ns != s) || (nht != hts) || (nhb != hbs);
        s = ns; hts = nht; hbs = nhb;
        if (!__any_sync(FULLM, ch)) break;
    }

    // sparse coalesced 255 writes (out pre-zeroed by memset; 255-only writes are
    // race-free against concurrent cross-tile CAS claims — all writers write 255)
    const unsigned obase = ((unsigned)bb << 20) + ((unsigned)gy0 << 10) + (unsigned)gx0;
#pragma unroll 4
    for (int r = 0; r < 32; r++) {
        unsigned long long m = __shfl_sync(FULLM, s, r);
        if ((m >> (lane + 1)) & 1ull)
            out[obase + ((unsigned)r << 10) + lane] = 255.0f;
    }

    // inline expansion from promoted interior pixels with out-of-tile weak neighbor
    unsigned long long prom = s & ~sm;
    unsigned long long wup = __shfl_up_sync(FULLM, wm, 1);
    if (lane == 0)  wup = ht_w;
    unsigned long long wdn = __shfl_down_sync(FULLM, wm, 1);
    if (lane == 31) wdn = hb_w;
    unsigned long long wvert = wup | wm | wdn;
    unsigned long long oow = 0;
    if (wvert & 1ull)            oow |= 2ull;
    if ((wvert >> 33) & 1ull)    oow |= (1ull << 32);
    if (lane == 0)  oow |= (ht_w | (ht_w << 1) | (ht_w >> 1));
    if (lane == 31) oow |= (hb_w | (hb_w << 1) | (hb_w >> 1));
    unsigned long long push = prom & oow & 0x1FFFFFFFEull;
    while (push) {
        int c = __ffsll((long long)push) - 1;
        push &= push - 1;
        unsigned p = ((unsigned)bb << 20) | ((unsigned)(gy0 + lane) << 10) | (unsigned)(gx0 + c - 1);
        expand_from(p, out, lo2, hi2, 0, 96);
    }
}

// ---------------- K3: persistent drain (backstop for spills) ----------------------
__device__ __forceinline__ void gsync() {
    __syncthreads();
    if (threadIdx.x == 0) {
        unsigned gen = atomicAdd(&g_bar_gen, 0u);
        __threadfence();
        if (atomicAdd(&g_bar_cnt, 1u) == gridDim.x - 1) {
            atomicExch(&g_bar_cnt, 0u);
            __threadfence();
            atomicAdd(&g_bar_gen, 1u);
        } else {
            while (atomicAdd(&g_bar_gen, 0u) == gen) __nanosleep(100);
        }
        __threadfence();
    }
    __syncthreads();
}

__global__ __launch_bounds__(256, 2) void k_drain(float* __restrict__ out) {
    int curq = 0;
    while (true) {
        unsigned n = atomicAdd(&g_ovfn[curq], 0u);
        if (n == 0u) break;
        if (n > OVF_CAP) n = OVF_CAP;
        const unsigned stride = gridDim.x * blockDim.x;
        for (unsigned i = blockIdx.x * blockDim.x + threadIdx.x; i < n; i += stride) {
            unsigned p = __ldcg(&g_ovfq[curq][i]);
            int bb = p >> 20;
            expand_from(p, out, g_lo2[bb], g_hi2[bb], curq ^ 1, 64);
        }
        gsync();
        if (blockIdx.x == 0 && threadIdx.x == 0) atomicExch(&g_ovfn[curq], 0u);
        gsync();
        curq ^= 1;
    }
}

// ---------------- launch ----------------
extern "C" void kernel_launch(void* const* d_in, const int* in_sizes, int n_in,
                              void* d_out, int out_size) {
    const float* img = (const float*)d_in[0];
    float* out = (float*)d_out;
    (void)in_sizes; (void)n_in; (void)out_size;

    k_init<<<1, 32>>>();
    cudaMemsetAsync(out, 0, (size_t)NPIX * sizeof(float));   // zero d_out at HBM speed
    dim3 b1(1024), g1(IMG_W / TS, IMG_H / TS, NBATCH);
    k_front<<<g1, b1>>>(img);
    k_thresh<<<1, 32>>>();
    k_seed<<<2048, 256>>>(out);
    k_drain<<<296, 256>>>(out);
}